// round 13
// baseline (speedup 1.0000x reference)
#include <cuda_runtime.h>

// QuantumLayer_9483287790225 — analytic closed form (R0 derivation).
//
// All single-qubit gates precede the CNOT ring, so the pre-ring state is a
// product state with per-wire
//   z_i = cos(pi*x_i) * ( cos(w_i) - sin(w_i)*sin(pi*x_i) )
// and the ring conjugates Z_j into prefix products:
//   <Z_0> = z_1*...*z_13 ;  <Z_j> = z_0*...*z_j  (j>=1)
//
// R12 == R9 resubmission (previous round died to a container/infra failure,
// zero signal). Body identical to R7 (best: 4.99us). Only variable under
// test: CTA granularity 32x128 -> 8x512 (same 4096 threads, same 16-lane
// warp scan) probing whether per-CTA distribution/drain cost is part of
// the 4.4us kernel floor. Kernel is launch-overhead bound: all pipes ~0%.

#define NQ 14
#define BATCH 256
#define PI_F 3.14159265358979323846f

__global__ void __launch_bounds__(512, 1)
quantum_layer_kernel(const float* __restrict__ x,
                     const float* __restrict__ weight,
                     float* __restrict__ out)
{
    const unsigned tid = blockIdx.x * blockDim.x + threadIdx.x;
    const unsigned sub = tid & 15u;          // wire index within 16-lane group
    const unsigned b   = tid >> 4;           // batch index

    // Clamped loads: padding lanes (14,15) reread wire 13 — in-bounds,
    // coalesced, no divergent predication on the LDG.
    const unsigned w = (sub < NQ) ? sub : (NQ - 1u);
    float xi = x[b * NQ + w];
    float wi = __ldg(weight + w);

    // z = cp * (cw - sw*sp)
    float a = PI_F * xi;
    float z = __cosf(a) * (__cosf(wi) - __sinf(wi) * __sinf(a));

    // Scan input: lane 0 and padding lanes contribute identity.
    float I = (sub == 0u || sub >= NQ) ? 1.0f : z;

    // 4-step inclusive product scan over 16-lane groups: I_j = z_1..z_j.
    // Select-operand form: unconditional FMUL fed by FSEL.
#pragma unroll
    for (int d = 1; d < 16; d <<= 1) {
        float t = __shfl_up_sync(0xffffffffu, I, d, 16);
        I *= (sub >= (unsigned)d) ? t : 1.0f;
    }

    float z0  = __shfl_sync(0xffffffffu, z, 0, 16);    // z_0
    float s13 = __shfl_sync(0xffffffffu, I, 13, 16);   // z_1..z_13

    if (sub < NQ) {
        float o = z0 * I;                  // <Z_j> = z_0 * z_1..z_j
        if (sub == 0u) o = s13;            // <Z_0> = z_1..z_13
        out[b * NQ + sub] = o;
    }
}

extern "C" void kernel_launch(void* const* d_in, const int* in_sizes, int n_in,
                              void* d_out, int out_size)
{
    const float* x      = (const float*)d_in[0];   // [256, 14]
    const float* weight = (const float*)d_in[1];   // [1, 14]
    float* out          = (float*)d_out;           // [256, 14]

    // Same 4096 threads, 4x fewer CTA distribution events: 8 x 512.
    quantum_layer_kernel<<<8, 512>>>(x, weight, out);
}

// round 14
// speedup vs baseline: 1.0188x; 1.0188x over previous
#include <cuda_runtime.h>

// QuantumLayer_9483287790225 — analytic closed form (R0 derivation). FINAL.
//
// All single-qubit gates precede the CNOT ring, so the pre-ring state is a
// product state with per-wire
//   z_i = cos(pi*x_i) * ( cos(w_i) - sin(w_i)*sin(pi*x_i) )
// and the ring conjugates Z_j into prefix products:
//   <Z_0> = z_1*...*z_13 ;  <Z_j> = z_0*...*z_j  (j>=1)
//
// R13: revert to R7, the measured optimum. Launch-shape search is complete
// and bracketed: 8x32 (5.18), 32x64 (6.18), 16x128 (5.18), 32x128 (4.99*),
// 8x512 (5.22). Four body architectures land within +-0.2us of kernel time
// with all pipes ~0% and issue <=3%: the kernel is at the launch/graph-
// replay floor. 16 lanes per batch, lane = wire; clamped loads (lanes
// 14/15 reread wire 13, in-bounds); select-operand scan (FSEL+FMUL, no
// predicated-execution arm).

#define NQ 14
#define BATCH 256
#define PI_F 3.14159265358979323846f

__global__ void __launch_bounds__(128, 1)
quantum_layer_kernel(const float* __restrict__ x,
                     const float* __restrict__ weight,
                     float* __restrict__ out)
{
    const unsigned tid = blockIdx.x * blockDim.x + threadIdx.x;
    const unsigned sub = tid & 15u;          // wire index within 16-lane group
    const unsigned b   = tid >> 4;           // batch index

    // Clamped loads: padding lanes (14,15) reread wire 13 — in-bounds,
    // coalesced, no divergent predication on the LDG.
    const unsigned w = (sub < NQ) ? sub : (NQ - 1u);
    float xi = x[b * NQ + w];
    float wi = __ldg(weight + w);

    // z = cp * (cw - sw*sp)
    float a = PI_F * xi;
    float z = __cosf(a) * (__cosf(wi) - __sinf(wi) * __sinf(a));

    // Scan input: lane 0 and padding lanes contribute identity.
    float I = (sub == 0u || sub >= NQ) ? 1.0f : z;

    // 4-step inclusive product scan over 16-lane groups: I_j = z_1..z_j.
    // Select-operand form: unconditional FMUL fed by FSEL.
#pragma unroll
    for (int d = 1; d < 16; d <<= 1) {
        float t = __shfl_up_sync(0xffffffffu, I, d, 16);
        I *= (sub >= (unsigned)d) ? t : 1.0f;
    }

    float z0  = __shfl_sync(0xffffffffu, z, 0, 16);    // z_0
    float s13 = __shfl_sync(0xffffffffu, I, 13, 16);   // z_1..z_13

    if (sub < NQ) {
        float o = z0 * I;                  // <Z_j> = z_0 * z_1..z_j
        if (sub == 0u) o = s13;            // <Z_0> = z_1..z_13
        out[b * NQ + sub] = o;
    }
}

extern "C" void kernel_launch(void* const* d_in, const int* in_sizes, int n_in,
                              void* d_out, int out_size)
{
    const float* x      = (const float*)d_in[0];   // [256, 14]
    const float* weight = (const float*)d_in[1];   // [1, 14]
    float* out          = (float*)d_out;           // [256, 14]

    // Measured-best shape: 256 batches x 16 lanes = 4096 threads, 32 x 128.
    quantum_layer_kernel<<<32, 128>>>(x, weight, out);
}